// round 4
// baseline (speedup 1.0000x reference)
#include <cuda_runtime.h>

// GenLoss fused single-kernel version.
// combined = mean_b( masked-mean_c( MAE(out,target)[b,c] ) ) - 0.01*mean(labels)/(epoch+1)
//
// Inputs: out_labels f32[16,1,30,30]=14400, out_images f32[16,3,512,512],
//         target_images f32[16,3,512,512], epoch int32[1]. Output: 1 float.
//
// Strategy: 768 image-reduce blocks + 8 label-reduce blocks in ONE launch.
// Each block writes its partial to __device__ scratch, then fence + atomicAdd
// on a counter; the last-arriving block performs the deterministic final fold
// and resets the counter (graph-replay safe).

#define PLANES      48
#define BPP         16
#define RBLOCKS     (PLANES * BPP)     // 768
#define LBLOCKS     8
#define TOTAL_BLK   (RBLOCKS + LBLOCKS)
#define THREADS     256
#define PLANE_ELEMS (512*512)
#define BLOCK_ELEMS (PLANE_ELEMS/BPP)          // 16384
#define VEC_ITERS   (BLOCK_ELEMS/(THREADS*4))  // 16

__device__ float g_psum[RBLOCKS];
__device__ int   g_pflag[RBLOCKS];
__device__ float g_lsum[LBLOCKS];
__device__ int   g_done;   // zero-initialized; reset by finalizer each launch

__global__ void __launch_bounds__(THREADS)
k_genloss(const float* __restrict__ out_img, const float* __restrict__ tgt_img,
          const float* __restrict__ labels, int n_labels,
          const int* __restrict__ epoch, float* __restrict__ out)
{
    const int tid = threadIdx.x;
    const int wid = tid >> 5;
    const int lid = tid & 31;

    __shared__ float ss[THREADS / 32];
    __shared__ int   sf[THREADS / 32];

    if (blockIdx.x < RBLOCKS) {
        // ---- image MAE partial for one 1/16th of a plane ----
        const int plane = blockIdx.x / BPP;
        const int sub   = blockIdx.x % BPP;
        const long base = (long)plane * PLANE_ELEMS + (long)sub * BLOCK_ELEMS;

        const float4* __restrict__ o = (const float4*)(out_img + base);
        const float4* __restrict__ t = (const float4*)(tgt_img + base);

        float s = 0.0f;
        int   flag = 0;
        #pragma unroll
        for (int j = 0; j < VEC_ITERS; j++) {
            float4 a = o[tid + j * THREADS];
            float4 b = t[tid + j * THREADS];
            s += fabsf(a.x - b.x) + fabsf(a.y - b.y)
               + fabsf(a.z - b.z) + fabsf(a.w - b.w);
            flag |= (b.x != 0.0f) | (b.y != 0.0f) | (b.z != 0.0f) | (b.w != 0.0f);
        }
        #pragma unroll
        for (int off = 16; off; off >>= 1) {
            s    += __shfl_down_sync(0xffffffffu, s, off);
            flag |= __shfl_down_sync(0xffffffffu, flag, off);
        }
        if (lid == 0) { ss[wid] = s; sf[wid] = flag; }
        __syncthreads();
        if (tid == 0) {
            float bs = 0.0f; int bf = 0;
            #pragma unroll
            for (int w = 0; w < THREADS / 32; w++) { bs += ss[w]; bf |= sf[w]; }
            g_psum[blockIdx.x]  = bs;
            g_pflag[blockIdx.x] = bf;
        }
    } else {
        // ---- label partial sum ----
        const int lb = blockIdx.x - RBLOCKS;
        float s = 0.0f;
        for (int i = lb * THREADS + tid; i < n_labels; i += LBLOCKS * THREADS)
            s += labels[i];
        #pragma unroll
        for (int off = 16; off; off >>= 1)
            s += __shfl_down_sync(0xffffffffu, s, off);
        if (lid == 0) ss[wid] = s;
        __syncthreads();
        if (tid == 0) {
            float bs = 0.0f;
            #pragma unroll
            for (int w = 0; w < THREADS / 32; w++) bs += ss[w];
            g_lsum[lb] = bs;
        }
    }

    // ---- last block finalizes (deterministic fold of all partials) ----
    __shared__ int isLast;
    if (tid == 0) {
        __threadfence();
        isLast = (atomicAdd(&g_done, 1) == TOTAL_BLK - 1);
    }
    __syncthreads();
    if (!isLast) return;

    __shared__ float plane_mae[PLANES];
    __shared__ int   plane_valid[PLANES];

    if (tid < PLANES) {
        float s = 0.0f; int f = 0;
        #pragma unroll
        for (int i = 0; i < BPP; i++) {
            s += g_psum[tid * BPP + i];
            f |= g_pflag[tid * BPP + i];
        }
        plane_mae[tid]   = s * (1.0f / (float)PLANE_ELEMS);
        plane_valid[tid] = f;
    }
    __syncthreads();

    if (tid == 0) {
        float lsum = 0.0f;
        #pragma unroll
        for (int i = 0; i < LBLOCKS; i++) lsum += g_lsum[i];
        const float lmean = lsum / (float)n_labels;

        float img = 0.0f;
        #pragma unroll
        for (int b = 0; b < 16; b++) {
            float tot = 0.0f, cnt = 0.0f;
            #pragma unroll
            for (int c = 0; c < 3; c++) {
                const int p = b * 3 + c;
                if (plane_valid[p]) { tot += plane_mae[p]; cnt += 1.0f; }
            }
            img += (cnt > 0.0f) ? (tot / cnt) : 0.0f;
        }
        img *= (1.0f / 16.0f);

        out[0] = img + 0.01f * (-lmean) / (float)(epoch[0] + 1);
        g_done = 0;   // reset for next graph replay
    }
}

extern "C" void kernel_launch(void* const* d_in, const int* in_sizes, int n_in,
                              void* d_out, int out_size)
{
    const float* labels  = (const float*)d_in[0];
    const float* out_img = (const float*)d_in[1];
    const float* tgt_img = (const float*)d_in[2];
    const int*   epoch   = (const int*)d_in[3];
    float*       out     = (float*)d_out;

    k_genloss<<<TOTAL_BLK, THREADS>>>(out_img, tgt_img, labels, in_sizes[0], epoch, out);
}

// round 5
// speedup vs baseline: 1.2718x; 1.2718x over previous
#include <cuda_runtime.h>

// GenLoss, two-kernel version with a FAST finalizer.
// combined = mean_b( masked-mean_c( MAE(out,target)[b,c] ) ) - 0.01*mean(labels)/(epoch+1)
//
// Kernel 1 (776 blocks): 768 blocks stream the two 48-plane images (float4,
//   L2-resident across graph replays, runs at the LTS cap) and write per-block
//   MAE partials + validity flags; 8 blocks produce label-sum partials.
// Kernel 2 (1 block): folds 768+8 partials via parallel vectorized loads into
//   smem (one latency round-trip, NOT a serial loop) and emits the scalar.
// No grid-wide counter -> no contended-atomic tail (R4's 10us regression).

#define PLANES      48
#define BPP         16
#define RBLOCKS     (PLANES * BPP)     // 768
#define LBLOCKS     8
#define THREADS     256
#define PLANE_ELEMS (512*512)
#define BLOCK_ELEMS (PLANE_ELEMS/BPP)          // 16384
#define VEC_ITERS   (BLOCK_ELEMS/(THREADS*4))  // 16

__device__ float g_psum[RBLOCKS];
__device__ int   g_pflag[RBLOCKS];
__device__ float g_lsum[LBLOCKS];

__global__ void __launch_bounds__(THREADS)
k_partials(const float* __restrict__ out_img, const float* __restrict__ tgt_img,
           const float* __restrict__ labels, int n_labels)
{
    const int tid = threadIdx.x;
    const int wid = tid >> 5;
    const int lid = tid & 31;

    __shared__ float ss[THREADS / 32];
    __shared__ int   sf[THREADS / 32];

    if (blockIdx.x < RBLOCKS) {
        const int plane = blockIdx.x / BPP;
        const int sub   = blockIdx.x % BPP;
        const long base = (long)plane * PLANE_ELEMS + (long)sub * BLOCK_ELEMS;

        const float4* __restrict__ o = (const float4*)(out_img + base);
        const float4* __restrict__ t = (const float4*)(tgt_img + base);

        float s = 0.0f;
        int   flag = 0;
        #pragma unroll
        for (int j = 0; j < VEC_ITERS; j++) {
            float4 a = o[tid + j * THREADS];
            float4 b = t[tid + j * THREADS];
            s += fabsf(a.x - b.x) + fabsf(a.y - b.y)
               + fabsf(a.z - b.z) + fabsf(a.w - b.w);
            flag |= (b.x != 0.0f) | (b.y != 0.0f) | (b.z != 0.0f) | (b.w != 0.0f);
        }
        #pragma unroll
        for (int off = 16; off; off >>= 1) {
            s    += __shfl_down_sync(0xffffffffu, s, off);
            flag |= __shfl_down_sync(0xffffffffu, flag, off);
        }
        if (lid == 0) { ss[wid] = s; sf[wid] = flag; }
        __syncthreads();
        if (tid == 0) {
            float bs = 0.0f; int bf = 0;
            #pragma unroll
            for (int w = 0; w < THREADS / 32; w++) { bs += ss[w]; bf |= sf[w]; }
            g_psum[blockIdx.x]  = bs;
            g_pflag[blockIdx.x] = bf;
        }
    } else {
        const int lb = blockIdx.x - RBLOCKS;
        float s = 0.0f;
        for (int i = lb * THREADS + tid; i < n_labels; i += LBLOCKS * THREADS)
            s += labels[i];
        #pragma unroll
        for (int off = 16; off; off >>= 1)
            s += __shfl_down_sync(0xffffffffu, s, off);
        if (lid == 0) ss[wid] = s;
        __syncthreads();
        if (tid == 0) {
            float bs = 0.0f;
            #pragma unroll
            for (int w = 0; w < THREADS / 32; w++) bs += ss[w];
            g_lsum[lb] = bs;
        }
    }
}

__global__ void __launch_bounds__(THREADS)
k_final(int n_labels, const int* __restrict__ epoch, float* __restrict__ out)
{
    __shared__ float sp[RBLOCKS];     // 3 KB
    __shared__ int   sfl[RBLOCKS];    // 3 KB
    __shared__ float plane_mae[PLANES];
    __shared__ int   plane_valid[PLANES];

    const int tid = threadIdx.x;

    // Parallel vectorized fetch of all partials: 192 float4 + 192 int4 loads,
    // all independent -> one memory latency round-trip.
    const float4* ps4 = (const float4*)g_psum;
    const int4*   pf4 = (const int4*)g_pflag;
    if (tid < RBLOCKS / 4) {
        float4 v = ps4[tid];
        int4   f = pf4[tid];
        sp[tid * 4 + 0] = v.x;  sp[tid * 4 + 1] = v.y;
        sp[tid * 4 + 2] = v.z;  sp[tid * 4 + 3] = v.w;
        sfl[tid * 4 + 0] = f.x; sfl[tid * 4 + 1] = f.y;
        sfl[tid * 4 + 2] = f.z; sfl[tid * 4 + 3] = f.w;
    }
    __syncthreads();

    if (tid < PLANES) {
        float s = 0.0f; int f = 0;
        #pragma unroll
        for (int i = 0; i < BPP; i++) {
            s += sp[tid * BPP + i];
            f |= sfl[tid * BPP + i];
        }
        plane_mae[tid]   = s * (1.0f / (float)PLANE_ELEMS);
        plane_valid[tid] = f;
    }
    __syncthreads();

    if (tid == 0) {
        float lsum = 0.0f;
        #pragma unroll
        for (int i = 0; i < LBLOCKS; i++) lsum += g_lsum[i];
        const float lmean = lsum / (float)n_labels;

        float img = 0.0f;
        #pragma unroll
        for (int b = 0; b < 16; b++) {
            float tot = 0.0f, cnt = 0.0f;
            #pragma unroll
            for (int c = 0; c < 3; c++) {
                const int p = b * 3 + c;
                if (plane_valid[p]) { tot += plane_mae[p]; cnt += 1.0f; }
            }
            img += (cnt > 0.0f) ? (tot / cnt) : 0.0f;
        }
        img *= (1.0f / 16.0f);

        out[0] = img + 0.01f * (-lmean) / (float)(epoch[0] + 1);
    }
}

extern "C" void kernel_launch(void* const* d_in, const int* in_sizes, int n_in,
                              void* d_out, int out_size)
{
    const float* labels  = (const float*)d_in[0];
    const float* out_img = (const float*)d_in[1];
    const float* tgt_img = (const float*)d_in[2];
    const int*   epoch   = (const int*)d_in[3];
    float*       out     = (float*)d_out;

    k_partials<<<RBLOCKS + LBLOCKS, THREADS>>>(out_img, tgt_img, labels, in_sizes[0]);
    k_final<<<1, THREADS>>>(in_sizes[0], epoch, out);
}